// round 8
// baseline (speedup 1.0000x reference)
#include <cuda_runtime.h>
#include <cstdint>

#define BATCH 8
#define HW 256
#define KK 13
#define HO 244   // 256 - 13 + 1

// ---- scratch (__device__ globals; no allocations allowed) ----
static __device__ float g_h1[(size_t)BATCH * 64 * HW * HW];    // conv1 out
static __device__ float g_h2[(size_t)BATCH * 64 * HW * HW];    // conv2 out
static __device__ float g_w [(size_t)BATCH * 169 * HO * HO];   // conv3 out
static __device__ float g_U2h[(size_t)16 * 64 * 64];           // W2 hi: [xi][oc][cin]
static __device__ float g_U2l[(size_t)16 * 64 * 64];           // W2 lo
static __device__ float g_U3h[(size_t)16 * 192 * 64];          // W3 hi (oc pad 192)
static __device__ float g_U3l[(size_t)16 * 192 * 64];          // W3 lo

__device__ __forceinline__ unsigned su(const void* p) {
    return (unsigned)__cvta_generic_to_shared(p);
}
__device__ __forceinline__ void cp4(unsigned dst, const void* src, int ok) {
    asm volatile("cp.async.ca.shared.global [%0], [%1], 4, %2;"
                 :: "r"(dst), "l"(src), "r"(ok ? 4 : 0));
}
__device__ __forceinline__ void cp16(unsigned dst, const void* src, int ok) {
    asm volatile("cp.async.cg.shared.global [%0], [%1], 16, %2;"
                 :: "r"(dst), "l"(src), "r"(ok ? 16 : 0));
}
#define CP_COMMIT() asm volatile("cp.async.commit_group;" ::: "memory")
#define CP_WAIT0()  asm volatile("cp.async.wait_group 0;"  ::: "memory")

__device__ __forceinline__ unsigned tf32b(float x) {
    unsigned r; asm("cvt.rna.tf32.f32 %0, %1;" : "=r"(r) : "f"(x)); return r;
}

__device__ __forceinline__ void mma8(float* d, unsigned a0, unsigned a1,
                                     unsigned a2, unsigned a3,
                                     unsigned b0, unsigned b1) {
    asm volatile(
        "mma.sync.aligned.m16n8k8.row.col.f32.tf32.tf32.f32 "
        "{%0,%1,%2,%3}, {%4,%5,%6,%7}, {%8,%9}, {%0,%1,%2,%3};"
        : "+f"(d[0]), "+f"(d[1]), "+f"(d[2]), "+f"(d[3])
        : "r"(a0), "r"(a1), "r"(a2), "r"(a3), "r"(b0), "r"(b1));
}

// ---------------------------------------------------------------------------
// Weight transform: U = G g G^T, split into tf32 hi + lo. Layout [xi][oc][cin].
__global__ void wino_wtrans(const float* __restrict__ Wt,
                            float* __restrict__ Uh, float* __restrict__ Ul,
                            int OC, int CIN, int OCp)
{
    int id = blockIdx.x * 256 + threadIdx.x;
    if (id >= OC * CIN) return;
    int oc = id / CIN, c = id % CIN;
    const float* g = Wt + (size_t)id * 9;
    float u[4][3];
#pragma unroll
    for (int j = 0; j < 3; ++j) {
        float g0 = g[j], g1 = g[3 + j], g2 = g[6 + j];
        u[0][j] = g0;
        u[1][j] = 0.5f * (g0 + g1 + g2);
        u[2][j] = 0.5f * (g0 - g1 + g2);
        u[3][j] = g2;
    }
#pragma unroll
    for (int i = 0; i < 4; ++i) {
        float a = u[i][0], b = u[i][1], cc = u[i][2];
        float U4[4] = { a, 0.5f * (a + b + cc), 0.5f * (a - b + cc), cc };
#pragma unroll
        for (int j = 0; j < 4; ++j) {
            float v  = U4[j];
            unsigned hb = tf32b(v);
            float hi = __uint_as_float(hb);
            size_t idx = ((size_t)(i * 4 + j) * OCp + oc) * CIN + c;
            Uh[idx] = hi;
            Ul[idx] = __uint_as_float(tf32b(v - hi));
        }
    }
}

// ---------------------------------------------------------------------------
// Winograd F(2x2,3x3) with mma.sync tf32 (3xTF32 split), fused transforms.
// CTA: 16x16 outputs (64 tiles) x 16 oc. 8 warps; warp w owns xi = 2w, 2w+1.
// smem floats:
//   sIn  [0, 5184):   2 bufs x 8ch x 18 x 18
//   sU   [5184,17472): 2 bufs x 2 splits x (16 xi x 16 oc x 12)
//   sV   [17472,44096): 2 splits x (16 xi x 64 tile x 13); sM aliases sV
#define IN_OFF  0
#define U_OFF   5184
#define V_OFF   17472
#define VS      13312              // floats per V split
#define SMEM_FLOATS 44096
#define SMEM_BYTES  (SMEM_FLOATS * 4)

template <bool RELU>
__global__ void __launch_bounds__(256, 1) wino_mma(
    const float* __restrict__ in,
    const float* __restrict__ Uh, const float* __restrict__ Ul,
    const float* __restrict__ bias, float* __restrict__ out,
    int outH, int outW, int inOff, int OC, int ocGroups, int OCp)
{
    extern __shared__ float smf[];
    float* sInBuf[2] = { smf + IN_OFF, smf + IN_OFF + 2592 };
    float* sUBuf [2] = { smf + U_OFF,  smf + U_OFF + 6144 };
    float* sV = smf + V_OFF;
    float* sM = smf + V_OFF;   // epilogue alias

    const int tid  = threadIdx.x;
    const int wid  = tid >> 5, lane = tid & 31;
    const int g    = lane >> 2, tq = lane & 3;

    const int b  = blockIdx.z / ocGroups;
    const int og = blockIdx.z % ocGroups;
    const int ocBase = og * 16;
    const int x0 = blockIdx.x * 16, y0 = blockIdx.y * 16;
    const float* inB = in + (size_t)b * 64 * HW * HW;

    // hoisted phase-A item mapping (2 items per thread)
    int paSrc[2], paT[2], paC[2];
#pragma unroll
    for (int q = 0; q < 2; ++q) {
        int p = tid + 256 * q;
        int c = p >> 6, t = p & 63;
        paSrc[q] = c * 324 + (t >> 3) * 36 + (t & 7) * 2;
        paT[q] = t; paC[q] = c;
    }

    float acc[2][4][2][4];
#pragma unroll
    for (int q = 0; q < 2; ++q)
#pragma unroll
        for (int m = 0; m < 4; ++m)
#pragma unroll
            for (int n = 0; n < 2; ++n)
#pragma unroll
                for (int e = 0; e < 4; ++e) acc[q][m][n][e] = 0.f;

    // ---- async stage of one 8-channel chunk ----
    auto stage = [&](int c0, float* sInD, float* sUD) {
#pragma unroll
        for (int k = 0; k < 11; ++k) {
            int idx = tid + 256 * k;
            if (idx < 2592) {
                int c  = idx / 324;
                int r  = idx - c * 324;
                int ry = r / 18, rx = r - ry * 18;
                int iy = y0 + inOff + ry - 1;
                int ix = x0 + inOff + rx - 1;
                int ok = (iy >= 0 && iy < HW && ix >= 0 && ix < HW);
                int cy = min(max(iy, 0), HW - 1);
                int cx = min(max(ix, 0), HW - 1);
                cp4(su(sInD + idx),
                    inB + ((size_t)(c0 + c) * HW + cy) * HW + cx, ok);
            }
        }
        // U: 2 splits x 16 xi x 16 oc x 2 c-halves = 1024 cp16
#pragma unroll
        for (int k = 0; k < 4; ++k) {
            int idx = tid + 256 * k;
            int s   = idx >> 9;
            int rem = idx & 511;
            int xi  = rem >> 5;
            int r2  = rem & 31;
            int oc  = r2 >> 1, hf = r2 & 1;
            int ocG = ocBase + oc;
            int ok  = (ocG < OC);
            const float* base = s ? Ul : Uh;
            const float* src = base + ((size_t)xi * OCp + (ok ? ocG : 0)) * 64
                                    + c0 + hf * 4;
            cp16(su(sUD + s * 3072 + xi * 192 + oc * 12 + hf * 4), src, ok);
        }
        CP_COMMIT();
    };

    stage(0, sInBuf[0], sUBuf[0]);

#pragma unroll 1
    for (int ci = 0; ci < 8; ++ci) {
        const int cur = ci & 1;
        float* sIn = sInBuf[cur];
        float* sU  = sUBuf[cur];

        CP_WAIT0();
        __syncthreads();
        if (ci < 7) stage((ci + 1) * 8, sInBuf[cur ^ 1], sUBuf[cur ^ 1]);

        // ---- phase A: V = B^T d B, tf32 hi/lo split -> sV ----
#pragma unroll
        for (int q = 0; q < 2; ++q) {
            const float2* base2 = (const float2*)(sIn + paSrc[q]);
            float d[4][4];
#pragma unroll
            for (int r = 0; r < 4; ++r) {
                float2 lo = base2[r * 9];
                float2 hi = base2[r * 9 + 1];
                d[r][0] = lo.x; d[r][1] = lo.y; d[r][2] = hi.x; d[r][3] = hi.y;
            }
            float z[4][4];
#pragma unroll
            for (int s = 0; s < 4; ++s) {
                z[0][s] = d[0][s] - d[2][s];
                z[1][s] = d[1][s] + d[2][s];
                z[2][s] = d[2][s] - d[1][s];
                z[3][s] = d[1][s] - d[3][s];
            }
            const int toff = paT[q] * 13 + paC[q];
#pragma unroll
            for (int i = 0; i < 4; ++i) {
                float w[4];
                w[0] = z[i][0] - z[i][2];
                w[1] = z[i][1] + z[i][2];
                w[2] = z[i][2] - z[i][1];
                w[3] = z[i][1] - z[i][3];
#pragma unroll
                for (int j = 0; j < 4; ++j) {
                    unsigned hb = tf32b(w[j]);
                    float hi = __uint_as_float(hb);
                    unsigned lb = tf32b(w[j] - hi);
                    int row = (i * 4 + j) * 832 + toff;
                    *(unsigned*)(sV + row)      = hb;
                    *(unsigned*)(sV + VS + row) = lb;
                }
            }
        }
        __syncthreads();

        // ---- phase B: mma.sync tf32, 3xTF32 per (xi, mtile, ntile) ----
#pragma unroll
        for (int q = 0; q < 2; ++q) {
            const int xi = wid * 2 + q;
            unsigned bh[2][2], bl[2][2];
#pragma unroll
            for (int nt = 0; nt < 2; ++nt) {
                const float* ub = sU + xi * 192 + nt * 96 + g * 12 + tq;
                bh[nt][0] = *(const unsigned*)(ub);
                bh[nt][1] = *(const unsigned*)(ub + 4);
                const float* ul2 = ub + 3072;
                bl[nt][0] = *(const unsigned*)(ul2);
                bl[nt][1] = *(const unsigned*)(ul2 + 4);
            }
#pragma unroll
            for (int mt = 0; mt < 4; ++mt) {
                const float* va = sV + xi * 832 + mt * 208 + g * 13 + tq;
                unsigned ah0 = *(const unsigned*)(va);
                unsigned ah1 = *(const unsigned*)(va + 104);
                unsigned ah2 = *(const unsigned*)(va + 4);
                unsigned ah3 = *(const unsigned*)(va + 108);
                const float* vl = va + VS;
                unsigned al0 = *(const unsigned*)(vl);
                unsigned al1 = *(const unsigned*)(vl + 104);
                unsigned al2 = *(const unsigned*)(vl + 4);
                unsigned al3 = *(const unsigned*)(vl + 108);
#pragma unroll
                for (int nt = 0; nt < 2; ++nt) {
                    mma8(acc[q][mt][nt], ah0, ah1, ah2, ah3,
                         bh[nt][0], bh[nt][1]);
                    mma8(acc[q][mt][nt], ah0, ah1, ah2, ah3,
                         bl[nt][0], bl[nt][1]);
                    mma8(acc[q][mt][nt], al0, al1, al2, al3,
                         bh[nt][0], bh[nt][1]);
                }
            }
        }
        __syncthreads();
    }

    // ---- phase C: Y = A^T M A, two oc halves through sM (aliases sV) ----
#pragma unroll 1
    for (int h = 0; h < 2; ++h) {
        // writers: scatter this half's accumulators to sM[(oc*64+tile)*17+xi]
#pragma unroll
        for (int q = 0; q < 2; ++q) {
            const int xi = wid * 2 + q;
#pragma unroll
            for (int mt = 0; mt < 4; ++mt) {
                int tile0 = mt * 16 + g;
                int ocl0  = 2 * tq;
                sM[((ocl0)     * 64 + tile0)     * 17 + xi] = acc[q][mt][h][0];
                sM[((ocl0 + 1) * 64 + tile0)     * 17 + xi] = acc[q][mt][h][1];
                sM[((ocl0)     * 64 + tile0 + 8) * 17 + xi] = acc[q][mt][h][2];
                sM[((ocl0 + 1) * 64 + tile0 + 8) * 17 + xi] = acc[q][mt][h][3];
            }
        }
        __syncthreads();
        for (int p = tid; p < 512; p += 256) {
            int oc = p >> 6, t = p & 63;
            int ocG = ocBase + h * 8 + oc;
            if (ocG < OC) {
                const float* src = sM + (oc * 64 + t) * 17;
                float m[4][4];
#pragma unroll
                for (int i = 0; i < 4; ++i)
#pragma unroll
                    for (int j = 0; j < 4; ++j) m[i][j] = src[i * 4 + j];
                float s0[4], s1[4];
#pragma unroll
                for (int j = 0; j < 4; ++j) {
                    s0[j] = m[0][j] + m[1][j] + m[2][j];
                    s1[j] = m[1][j] - m[2][j] - m[3][j];
                }
                float bv = bias[ocG];
                float y00 = s0[0] + s0[1] + s0[2] + bv;
                float y01 = s0[1] - s0[2] - s0[3] + bv;
                float y10 = s1[0] + s1[1] + s1[2] + bv;
                float y11 = s1[1] - s1[2] - s1[3] + bv;
                if (RELU) {
                    y00 = fmaxf(y00, 0.f); y01 = fmaxf(y01, 0.f);
                    y10 = fmaxf(y10, 0.f); y11 = fmaxf(y11, 0.f);
                }
                int oy = y0 + (t >> 3) * 2;
                int ox = x0 + (t & 7) * 2;
                float* o0 = out + ((size_t)((size_t)b * OC + ocG)
                                   * outH + oy) * outW + ox;
                if (oy < outH) {
                    if (ox     < outW) o0[0] = y00;
                    if (ox + 1 < outW) o0[1] = y01;
                }
                if (oy + 1 < outH) {
                    if (ox     < outW) o0[outW]     = y10;
                    if (ox + 1 < outW) o0[outW + 1] = y11;
                }
            }
        }
        __syncthreads();
    }
}

// ---------------------------------------------------------------------------
// conv1 (1 -> 64): direct, register-tiled (cheap layer).
template <int CIN, int CC, bool RELU>
__global__ void __launch_bounds__(256) conv3x3_v3(
    const float* __restrict__ in, int inH, int inW,
    const float* __restrict__ Wt, const float* __restrict__ bias,
    float* __restrict__ out, int outH, int outW,
    int inOff, int OC, int ocGroups)
{
    __shared__ float sIn[CC][34][34];
    __shared__ float sW[16][CC][9];

    const int tx = threadIdx.x, ty = threadIdx.y;
    const int tid = ty * 16 + tx;
    const int b  = blockIdx.z / ocGroups;
    const int og = blockIdx.z % ocGroups;
    const int ocBase = og * 16;
    const int x0 = blockIdx.x * 32, y0 = blockIdx.y * 32;

    float acc[16][4];
#pragma unroll
    for (int o = 0; o < 16; ++o)
#pragma unroll
        for (int p = 0; p < 4; ++p) acc[o][p] = 0.f;

    const float* inB = in + (size_t)b * CIN * inH * inW;

    for (int c0 = 0; c0 < CIN; c0 += CC) {
        for (int idx = tid; idx < CC * 34 * 34; idx += 256) {
            int c  = idx / (34 * 34);
            int r  = idx % (34 * 34);
            int ry = r / 34, rx = r % 34;
            int iy = y0 + inOff + ry - 1;
            int ix = x0 + inOff + rx - 1;
            float v = 0.f;
            if (iy >= 0 && iy < inH && ix >= 0 && ix < inW)
                v = inB[((size_t)(c0 + c) * inH + iy) * inW + ix];
            sIn[c][ry][rx] = v;
        }
        for (int idx = tid; idx < 16 * CC * 9; idx += 256) {
            int o = idx / (CC * 9);
            int r = idx % (CC * 9);
            int c = r / 9, tt = r % 9;
            int oc = ocBase + o;
            sW[o][c][tt] = (oc < OC)
                ? Wt[((size_t)oc * CIN + (c0 + c)) * 9 + tt] : 0.f;
        }
        __syncthreads();

#pragma unroll 1
        for (int c = 0; c < CC; ++c) {
            float v[4][4];
#pragma unroll
            for (int u = 0; u < 4; ++u)
#pragma unroll
                for (int w = 0; w < 4; ++w)
                    v[u][w] = sIn[c][2 * ty + u][2 * tx + w];
#pragma unroll
            for (int o = 0; o < 16; ++o) {
#pragma unroll
                for (int ky = 0; ky < 3; ++ky) {
#pragma unroll
                    for (int kx = 0; kx < 3; ++kx) {
                        float wv = sW[o][c][ky * 3 + kx];
                        acc[o][0] = fmaf(v[ky    ][kx    ], wv, acc[o][0]);
                        acc[o][1] = fmaf(v[ky    ][kx + 1], wv, acc[o][1]);
                        acc[o][2] = fmaf(v[ky + 1][kx    ], wv, acc[o][2]);
                        acc[o][3] = fmaf(v[ky + 1][kx + 1], wv, acc[o][3]);
                    }
                }
            }
        }
        __syncthreads();
    }

    const int ox = x0 + 2 * tx;
#pragma unroll
    for (int o = 0; o < 16; ++o) {
        int oc = ocBase + o;
        if (oc >= OC) continue;
        float bv = bias[oc];
#pragma unroll
        for (int py = 0; py < 2; ++py) {
            int oy = y0 + 2 * ty + py;
            if (oy >= outH || ox >= outW) continue;
            float r0 = acc[o][2 * py    ] + bv;
            float r1 = acc[o][2 * py + 1] + bv;
            if (RELU) { r0 = fmaxf(r0, 0.f); r1 = fmaxf(r1, 0.f); }
            *(float2*)&out[((size_t)((size_t)b * OC + oc) * outH + oy) * outW + ox]
                = make_float2(r0, r1);
        }
    }
}

// y[b,i,j] = sum_{u,v} x[b, i+u, j+v] * w[b, u*13+v, i, j]
__global__ void __launch_bounds__(256) agg_kernel(
    const float* __restrict__ x, float* __restrict__ y)
{
    int id = blockIdx.x * 256 + threadIdx.x;
    if (id >= BATCH * HO * HO) return;
    int j = id % HO;
    int i = (id / HO) % HO;
    int b = id / (HO * HO);
    const float* xb = x + (size_t)b * HW * HW;
    const float* wb = g_w + (size_t)b * 169 * HO * HO + (size_t)i * HO + j;
    float acc = 0.f;
    for (int u = 0; u < KK; ++u) {
        const float* xr = xb + (size_t)(i + u) * HW + j;
#pragma unroll
        for (int v = 0; v < KK; ++v)
            acc = fmaf(xr[v], wb[(size_t)(u * KK + v) * HO * HO], acc);
    }
    y[id] = acc;
}

extern "C" void kernel_launch(void* const* d_in, const int* in_sizes, int n_in,
                              void* d_out, int out_size)
{
    const float* x  = (const float*)d_in[0];
    const float* W1 = (const float*)d_in[1];
    const float* b1 = (const float*)d_in[2];
    const float* W2 = (const float*)d_in[3];
    const float* b2 = (const float*)d_in[4];
    const float* W3 = (const float*)d_in[5];
    const float* b3 = (const float*)d_in[6];
    float* y = (float*)d_out;

    float *h1, *h2, *w, *U2h, *U2l, *U3h, *U3l;
    cudaGetSymbolAddress((void**)&h1,  g_h1);
    cudaGetSymbolAddress((void**)&h2,  g_h2);
    cudaGetSymbolAddress((void**)&w,   g_w);
    cudaGetSymbolAddress((void**)&U2h, g_U2h);
    cudaGetSymbolAddress((void**)&U2l, g_U2l);
    cudaGetSymbolAddress((void**)&U3h, g_U3h);
    cudaGetSymbolAddress((void**)&U3l, g_U3l);

    static int inited = 0;
    if (!inited) {
        cudaFuncSetAttribute(wino_mma<true>,
            cudaFuncAttributeMaxDynamicSharedMemorySize, SMEM_BYTES);
        cudaFuncSetAttribute(wino_mma<false>,
            cudaFuncAttributeMaxDynamicSharedMemorySize, SMEM_BYTES);
        inited = 1;
    }

    // weight transforms (tiny)
    wino_wtrans<<<(64 * 64 + 255) / 256, 256>>>(W2, U2h, U2l, 64, 64, 64);
    wino_wtrans<<<(169 * 64 + 255) / 256, 256>>>(W3, U3h, U3l, 169, 64, 192);

    // conv1: 1 -> 64, relu (direct)
    conv3x3_v3<1, 1, true><<<dim3(8, 8, BATCH * 4), dim3(16, 16)>>>(
        x, HW, HW, W1, b1, h1, HW, HW, 0, 64, 4);

    // conv2: 64 -> 64, relu (mma.sync tf32 winograd)
    wino_mma<true><<<dim3(16, 16, BATCH * 4), 256, SMEM_BYTES>>>(
        h1, U2h, U2l, b2, h2, HW, HW, 0, 64, 4, 64);

    // conv3: 64 -> 169 (pad 192, 11 groups), cropped interior (244x244, +6)
    wino_mma<false><<<dim3(16, 16, BATCH * 11), 256, SMEM_BYTES>>>(
        h2, U3h, U3l, b3, w, HO, HO, 6, 169, 11, 192);

    // final per-pixel 13x13 patch dot-product
    int n = BATCH * HO * HO;
    agg_kernel<<<(n + 255) / 256, 256>>>(x, y);
}

// round 9
// speedup vs baseline: 1.6425x; 1.6425x over previous
#include <cuda_runtime.h>
#include <cuda_bf16.h>
#include <cstdint>

#define BATCH 8
#define HW 256
#define KK 13
#define HO 244   // 256 - 13 + 1

// ---- scratch (__device__ globals; no allocations allowed) ----
static __device__ float    g_h1[(size_t)BATCH * 64 * HW * HW];
static __device__ float    g_h2[(size_t)BATCH * 64 * HW * HW];
static __device__ float    g_w [(size_t)BATCH * 169 * HO * HO];
static __device__ unsigned g_U2h[(size_t)16 * 64 * 32];    // bf16x2 [xi][oc][cpair]
static __device__ unsigned g_U2l[(size_t)16 * 64 * 32];
static __device__ unsigned g_U3h[(size_t)16 * 176 * 32];   // oc padded to 176
static __device__ unsigned g_U3l[(size_t)16 * 176 * 32];

__device__ __forceinline__ unsigned su(const void* p) {
    return (unsigned)__cvta_generic_to_shared(p);
}
__device__ __forceinline__ void cp4(unsigned dst, const void* src, int ok) {
    asm volatile("cp.async.ca.shared.global [%0], [%1], 4, %2;"
                 :: "r"(dst), "l"(src), "r"(ok ? 4 : 0));
}
__device__ __forceinline__ void cp16(unsigned dst, const void* src, int ok) {
    asm volatile("cp.async.cg.shared.global [%0], [%1], 16, %2;"
                 :: "r"(dst), "l"(src), "r"(ok ? 16 : 0));
}
#define CP_COMMIT() asm volatile("cp.async.commit_group;" ::: "memory")
#define CP_WAIT0()  asm volatile("cp.async.wait_group 0;"  ::: "memory")

__device__ __forceinline__ void mma16(float* d, unsigned a0, unsigned a1,
                                      unsigned a2, unsigned a3,
                                      unsigned b0, unsigned b1) {
    asm volatile(
        "mma.sync.aligned.m16n8k16.row.col.f32.bf16.bf16.f32 "
        "{%0,%1,%2,%3}, {%4,%5,%6,%7}, {%8,%9}, {%0,%1,%2,%3};"
        : "+f"(d[0]), "+f"(d[1]), "+f"(d[2]), "+f"(d[3])
        : "r"(a0), "r"(a1), "r"(a2), "r"(a3), "r"(b0), "r"(b1));
}

// split x into bf16 hi + bf16 lo residual
__device__ __forceinline__ void bsplit(float a, float b,
                                       unsigned& hi, unsigned& lo) {
    __nv_bfloat162 h = __floats2bfloat162_rn(a, b);
    float ra = a - __bfloat162float(h.x);
    float rb = b - __bfloat162float(h.y);
    __nv_bfloat162 l = __floats2bfloat162_rn(ra, rb);
    hi = *(unsigned*)&h;
    lo = *(unsigned*)&l;
}

// ---------------------------------------------------------------------------
// Weight transform: U = G g G^T, bf16 hi/lo packed per cin-pair.
// Layout: U[xi][oc][cpair], cpair = cin/2 (32 pairs of 64 cin).
__global__ void wino_wtrans(const float* __restrict__ Wt,
                            unsigned* __restrict__ Uh, unsigned* __restrict__ Ul,
                            int OC, int OCp)
{
    int id = blockIdx.x * 256 + threadIdx.x;
    if (id >= OCp * 32) return;
    int oc = id / 32, cp = id % 32;
    float UA[16], UB[16];
#pragma unroll
    for (int half = 0; half < 2; ++half) {
        float* dst = half ? UB : UA;
        int c = 2 * cp + half;
        if (oc < OC) {
            const float* g = Wt + ((size_t)oc * 64 + c) * 9;
            float u[4][3];
#pragma unroll
            for (int j = 0; j < 3; ++j) {
                float g0 = g[j], g1 = g[3 + j], g2 = g[6 + j];
                u[0][j] = g0;
                u[1][j] = 0.5f * (g0 + g1 + g2);
                u[2][j] = 0.5f * (g0 - g1 + g2);
                u[3][j] = g2;
            }
#pragma unroll
            for (int i = 0; i < 4; ++i) {
                float a = u[i][0], b = u[i][1], cc = u[i][2];
                dst[i * 4 + 0] = a;
                dst[i * 4 + 1] = 0.5f * (a + b + cc);
                dst[i * 4 + 2] = 0.5f * (a - b + cc);
                dst[i * 4 + 3] = cc;
            }
        } else {
#pragma unroll
            for (int k = 0; k < 16; ++k) dst[k] = 0.f;
        }
    }
#pragma unroll
    for (int xi = 0; xi < 16; ++xi) {
        unsigned hi, lo;
        bsplit(UA[xi], UB[xi], hi, lo);
        size_t idx = ((size_t)xi * OCp + oc) * 32 + cp;
        Uh[idx] = hi;
        Ul[idx] = lo;
    }
}

// ---------------------------------------------------------------------------
// Winograd F(2x2,3x3), bf16-split mma.sync m16n8k16.
// CTA: 16x16 outputs (64 tiles) x 16 oc. 8 warps; warp w owns xi = 2w, 2w+1.
// cin in 4 chunks of 16 (one k16 mma per split per chunk).
// smem (float/u32 units):
//   IN  [0, 10368):      2 bufs x 16ch x 18 x 18
//   U   [10368, 22656):  2 bufs x 2 spl x 16xi x 16oc x 12 (u32, stride 12)
//   V   [22656, 41088):  2 spl x 16xi x 64t x 9 (u32, stride 9); sM aliases
#define IN_OFF  0
#define U_OFF   10368
#define V_OFF   22656
#define SMEM_BYTES (41088 * 4)

template <bool RELU>
__global__ void __launch_bounds__(256, 1) wino_mma(
    const float* __restrict__ in,
    const unsigned* __restrict__ Uh, const unsigned* __restrict__ Ul,
    const float* __restrict__ bias, float* __restrict__ out,
    int outH, int outW, int inOff, int OC, int ocGroups, int OCp)
{
    extern __shared__ float smf[];
    float*    sInBuf[2] = { smf, smf + 5184 };
    unsigned* sU32 = (unsigned*)(smf + U_OFF);   // + buf*6144 + s*3072
    unsigned* sV32 = (unsigned*)(smf + V_OFF);   // + s*9216 + xi*576 + t*9 + cp
    float*    sM   = smf + V_OFF;                // epilogue alias

    const int tid  = threadIdx.x;
    const int wid  = tid >> 5, lane = tid & 31;
    const int g    = lane >> 2, tq = lane & 3;

    const int b  = blockIdx.z / ocGroups;
    const int og = blockIdx.z % ocGroups;
    const int ocBase = og * 16;
    const int x0 = blockIdx.x * 16, y0 = blockIdx.y * 16;
    const float* inB = in + (size_t)b * 64 * HW * HW;

    // hoisted phase-A item mapping (2 items per thread): p -> (cpair, tile)
    int paT[2], paCP[2], paBase[2];
#pragma unroll
    for (int q = 0; q < 2; ++q) {
        int p = tid + 256 * q;
        paCP[q] = p >> 6;          // 0..7
        paT[q]  = p & 63;
        paBase[q] = (paT[q] >> 3) * 36 + (paT[q] & 7) * 2;
    }

    float acc[2][4][2][4];
#pragma unroll
    for (int q = 0; q < 2; ++q)
#pragma unroll
        for (int m = 0; m < 4; ++m)
#pragma unroll
            for (int n = 0; n < 2; ++n)
#pragma unroll
                for (int e = 0; e < 4; ++e) acc[q][m][n][e] = 0.f;

    // ---- async stage of one 16-channel chunk ----
    auto stage = [&](int ci, float* sInD, unsigned uOff) {
#pragma unroll
        for (int k = 0; k < 21; ++k) {
            int idx = tid + 256 * k;
            if (idx < 5184) {
                int c  = idx / 324;
                int r  = idx - c * 324;
                int ry = r / 18, rx = r - ry * 18;
                int iy = y0 + inOff + ry - 1;
                int ix = x0 + inOff + rx - 1;
                int ok = (iy >= 0 && iy < HW && ix >= 0 && ix < HW);
                int cy = min(max(iy, 0), HW - 1);
                int cx = min(max(ix, 0), HW - 1);
                cp4(su(sInD + idx),
                    inB + ((size_t)(ci * 16 + c) * HW + cy) * HW + cx, ok);
            }
        }
        // U: 2 spl x 16 xi x 16 oc x 2 halves = 1024 cp16
#pragma unroll
        for (int k = 0; k < 4; ++k) {
            int idx = tid + 256 * k;
            int s   = idx >> 9;
            int rem = idx & 511;
            int xi  = rem >> 5;
            int r2  = rem & 31;
            int oc  = r2 >> 1, hf = r2 & 1;
            int ocG = ocBase + oc;
            int ok  = (ocG < OC);
            const unsigned* base = s ? Ul : Uh;
            const unsigned* src = base + ((size_t)xi * OCp + (ok ? ocG : 0)) * 32
                                       + ci * 8 + hf * 4;
            cp16(su(sU32 + uOff + s * 3072 + xi * 192 + oc * 12 + hf * 4),
                 src, ok);
        }
        CP_COMMIT();
    };

    stage(0, sInBuf[0], 0);

#pragma unroll 1
    for (int ci = 0; ci < 4; ++ci) {
        const int cur = ci & 1;
        float* sIn = sInBuf[cur];
        const unsigned uOff = cur ? 6144u : 0u;

        CP_WAIT0();
        __syncthreads();
        if (ci < 3) stage(ci + 1, sInBuf[cur ^ 1], cur ? 0u : 6144u);

        // ---- phase A: V = B^T d B for a cin pair, bf16 hi/lo packed ----
#pragma unroll
        for (int q = 0; q < 2; ++q) {
            float zA[4][4], zB[4][4];
#pragma unroll
            for (int half = 0; half < 2; ++half) {
                const float2* base2 = (const float2*)
                    (sIn + (2 * paCP[q] + half) * 324 + paBase[q]);
                float d[4][4];
#pragma unroll
                for (int r = 0; r < 4; ++r) {
                    float2 lo = base2[r * 9];
                    float2 hi = base2[r * 9 + 1];
                    d[r][0] = lo.x; d[r][1] = lo.y;
                    d[r][2] = hi.x; d[r][3] = hi.y;
                }
                float (*z)[4] = half ? zB : zA;
#pragma unroll
                for (int s = 0; s < 4; ++s) {
                    z[0][s] = d[0][s] - d[2][s];
                    z[1][s] = d[1][s] + d[2][s];
                    z[2][s] = d[2][s] - d[1][s];
                    z[3][s] = d[1][s] - d[3][s];
                }
            }
            const int voff = paT[q] * 9 + paCP[q];
#pragma unroll
            for (int i = 0; i < 4; ++i) {
                float wA[4], wB[4];
                wA[0] = zA[i][0] - zA[i][2];  wB[0] = zB[i][0] - zB[i][2];
                wA[1] = zA[i][1] + zA[i][2];  wB[1] = zB[i][1] + zB[i][2];
                wA[2] = zA[i][2] - zA[i][1];  wB[2] = zB[i][2] - zB[i][1];
                wA[3] = zA[i][1] - zA[i][3];  wB[3] = zB[i][1] - zB[i][3];
#pragma unroll
                for (int j = 0; j < 4; ++j) {
                    unsigned hi, lo;
                    bsplit(wA[j], wB[j], hi, lo);
                    int row = (i * 4 + j) * 576 + voff;
                    sV32[row]        = hi;
                    sV32[9216 + row] = lo;
                }
            }
        }
        __syncthreads();

        // ---- phase B: bf16 m16n8k16, 3 cross-term mmas ----
#pragma unroll
        for (int q = 0; q < 2; ++q) {
            const int xi = wid * 2 + q;
            unsigned bh[2][2], bl[2][2];
#pragma unroll
            for (int nt = 0; nt < 2; ++nt) {
                const unsigned* ub = sU32 + uOff + xi * 192
                                   + (nt * 8 + g) * 12;
                bh[nt][0] = ub[tq];
                bh[nt][1] = ub[tq + 4];
                bl[nt][0] = ub[3072 + tq];
                bl[nt][1] = ub[3072 + tq + 4];
            }
#pragma unroll
            for (int mt = 0; mt < 4; ++mt) {
                const unsigned* va = sV32 + xi * 576 + (mt * 16 + g) * 9;
                unsigned ah0 = va[tq];
                unsigned ah1 = va[72 + tq];        // +8 rows
                unsigned ah2 = va[tq + 4];
                unsigned ah3 = va[72 + tq + 4];
                unsigned al0 = va[9216 + tq];
                unsigned al1 = va[9216 + 72 + tq];
                unsigned al2 = va[9216 + tq + 4];
                unsigned al3 = va[9216 + 72 + tq + 4];
#pragma unroll
                for (int nt = 0; nt < 2; ++nt) {
                    mma16(acc[q][mt][nt], ah0, ah1, ah2, ah3,
                          bh[nt][0], bh[nt][1]);
                    mma16(acc[q][mt][nt], ah0, ah1, ah2, ah3,
                          bl[nt][0], bl[nt][1]);
                    mma16(acc[q][mt][nt], al0, al1, al2, al3,
                          bh[nt][0], bh[nt][1]);
                }
            }
        }
        __syncthreads();
    }

    // ---- phase C: Y = A^T M A, two oc halves through sM (aliases sV) ----
#pragma unroll 1
    for (int h = 0; h < 2; ++h) {
#pragma unroll
        for (int q = 0; q < 2; ++q) {
            const int xi = wid * 2 + q;
#pragma unroll
            for (int mt = 0; mt < 4; ++mt) {
                int tile0 = mt * 16 + g;
                int ocl0  = 2 * tq;
                sM[((ocl0)     * 64 + tile0)     * 17 + xi] = acc[q][mt][h][0];
                sM[((ocl0 + 1) * 64 + tile0)     * 17 + xi] = acc[q][mt][h][1];
                sM[((ocl0)     * 64 + tile0 + 8) * 17 + xi] = acc[q][mt][h][2];
                sM[((ocl0 + 1) * 64 + tile0 + 8) * 17 + xi] = acc[q][mt][h][3];
            }
        }
        __syncthreads();
        for (int p = tid; p < 512; p += 256) {
            int oc = p >> 6, t = p & 63;
            int ocG = ocBase + h * 8 + oc;
            if (ocG < OC) {
                const float* src = sM + (oc * 64 + t) * 17;
                float m[4][4];
#pragma unroll
                for (int i = 0; i < 4; ++i)
#pragma unroll
                    for (int j = 0; j < 4; ++j) m[i][j] = src[i * 4 + j];
                float s0[4], s1[4];
#pragma unroll
                for (int j = 0; j < 4; ++j) {
                    s0[j] = m[0][j] + m[1][j] + m[2][j];
                    s1[j] = m[1][j] - m[2][j] - m[3][j];
                }
                float bv = bias[ocG];
                float y00 = s0[0] + s0[1] + s0[2] + bv;
                float y01 = s0[1] - s0[2] - s0[3] + bv;
                float y10 = s1[0] + s1[1] + s1[2] + bv;
                float y11 = s1[1] - s1[2] - s1[3] + bv;
                if (RELU) {
                    y00 = fmaxf(y00, 0.f); y01 = fmaxf(y01, 0.f);
                    y10 = fmaxf(y10, 0.f); y11 = fmaxf(y11, 0.f);
                }
                int oy = y0 + (t >> 3) * 2;
                int ox = x0 + (t & 7) * 2;
                float* o0 = out + ((size_t)((size_t)b * OC + ocG)
                                   * outH + oy) * outW + ox;
                if (oy < outH) {
                    if (ox     < outW) o0[0] = y00;
                    if (ox + 1 < outW) o0[1] = y01;
                }
                if (oy + 1 < outH) {
                    if (ox     < outW) o0[outW]     = y10;
                    if (ox + 1 < outW) o0[outW + 1] = y11;
                }
            }
        }
        __syncthreads();
    }
}

// ---------------------------------------------------------------------------
// conv1 (1 -> 64): direct, register-tiled (cheap layer).
template <int CIN, int CC, bool RELU>
__global__ void __launch_bounds__(256) conv3x3_v3(
    const float* __restrict__ in, int inH, int inW,
    const float* __restrict__ Wt, const float* __restrict__ bias,
    float* __restrict__ out, int outH, int outW,
    int inOff, int OC, int ocGroups)
{
    __shared__ float sIn[CC][34][34];
    __shared__ float sW[16][CC][9];

    const int tx = threadIdx.x, ty = threadIdx.y;
    const int tid = ty * 16 + tx;
    const int b  = blockIdx.z / ocGroups;
    const int og = blockIdx.z % ocGroups;
    const int ocBase = og * 16;
    const int x0 = blockIdx.x * 32, y0 = blockIdx.y * 32;

    float acc[16][4];
#pragma unroll
    for (int o = 0; o < 16; ++o)
#pragma unroll
        for (int p = 0; p < 4; ++p) acc[o][p] = 0.f;

    const float* inB = in + (size_t)b * CIN * inH * inW;

    for (int c0 = 0; c0 < CIN; c0 += CC) {
        for (int idx = tid; idx < CC * 34 * 34; idx += 256) {
            int c  = idx / (34 * 34);
            int r  = idx % (34 * 34);
            int ry = r / 34, rx = r % 34;
            int iy = y0 + inOff + ry - 1;
            int ix = x0 + inOff + rx - 1;
            float v = 0.f;
            if (iy >= 0 && iy < inH && ix >= 0 && ix < inW)
                v = inB[((size_t)(c0 + c) * inH + iy) * inW + ix];
            sIn[c][ry][rx] = v;
        }
        for (int idx = tid; idx < 16 * CC * 9; idx += 256) {
            int o = idx / (CC * 9);
            int r = idx % (CC * 9);
            int c = r / 9, tt = r % 9;
            int oc = ocBase + o;
            sW[o][c][tt] = (oc < OC)
                ? Wt[((size_t)oc * CIN + (c0 + c)) * 9 + tt] : 0.f;
        }
        __syncthreads();

#pragma unroll 1
        for (int c = 0; c < CC; ++c) {
            float v[4][4];
#pragma unroll
            for (int u = 0; u < 4; ++u)
#pragma unroll
                for (int w = 0; w < 4; ++w)
                    v[u][w] = sIn[c][2 * ty + u][2 * tx + w];
#pragma unroll
            for (int o = 0; o < 16; ++o) {
#pragma unroll
                for (int ky = 0; ky < 3; ++ky) {
#pragma unroll
                    for (int kx = 0; kx < 3; ++kx) {
                        float wv = sW[o][c][ky * 3 + kx];
                        acc[o][0] = fmaf(v[ky    ][kx    ], wv, acc[o][0]);
                        acc[o][1] = fmaf(v[ky    ][kx + 1], wv, acc[o][1]);
                        acc[o][2] = fmaf(v[ky + 1][kx    ], wv, acc[o][2]);
                        acc[o][3] = fmaf(v[ky + 1][kx + 1], wv, acc[o][3]);
                    }
                }
            }
        }
        __syncthreads();
    }

    const int ox = x0 + 2 * tx;
#pragma unroll
    for (int o = 0; o < 16; ++o) {
        int oc = ocBase + o;
        if (oc >= OC) continue;
        float bv = bias[oc];
#pragma unroll
        for (int py = 0; py < 2; ++py) {
            int oy = y0 + 2 * ty + py;
            if (oy >= outH || ox >= outW) continue;
            float r0 = acc[o][2 * py    ] + bv;
            float r1 = acc[o][2 * py + 1] + bv;
            if (RELU) { r0 = fmaxf(r0, 0.f); r1 = fmaxf(r1, 0.f); }
            *(float2*)&out[((size_t)((size_t)b * OC + oc) * outH + oy) * outW + ox]
                = make_float2(r0, r1);
        }
    }
}

// y[b,i,j] = sum_{u,v} x[b, i+u, j+v] * w[b, u*13+v, i, j]
__global__ void __launch_bounds__(256) agg_kernel(
    const float* __restrict__ x, float* __restrict__ y)
{
    int id = blockIdx.x * 256 + threadIdx.x;
    if (id >= BATCH * HO * HO) return;
    int j = id % HO;
    int i = (id / HO) % HO;
    int b = id / (HO * HO);
    const float* xb = x + (size_t)b * HW * HW;
    const float* wb = g_w + (size_t)b * 169 * HO * HO + (size_t)i * HO + j;
    float acc = 0.f;
    for (int u = 0; u < KK; ++u) {
        const float* xr = xb + (size_t)(i + u) * HW + j;
#pragma unroll
        for (int v = 0; v < KK; ++v)
            acc = fmaf(xr[v], wb[(size_t)(u * KK + v) * HO * HO], acc);
    }
    y[id] = acc;
}

extern "C" void kernel_launch(void* const* d_in, const int* in_sizes, int n_in,
                              void* d_out, int out_size)
{
    const float* x  = (const float*)d_in[0];
    const float* W1 = (const float*)d_in[1];
    const float* b1 = (const float*)d_in[2];
    const float* W2 = (const float*)d_in[3];
    const float* b2 = (const float*)d_in[4];
    const float* W3 = (const float*)d_in[5];
    const float* b3 = (const float*)d_in[6];
    float* y = (float*)d_out;

    float *h1, *h2, *w;
    unsigned *U2h, *U2l, *U3h, *U3l;
    cudaGetSymbolAddress((void**)&h1,  g_h1);
    cudaGetSymbolAddress((void**)&h2,  g_h2);
    cudaGetSymbolAddress((void**)&w,   g_w);
    cudaGetSymbolAddress((void**)&U2h, g_U2h);
    cudaGetSymbolAddress((void**)&U2l, g_U2l);
    cudaGetSymbolAddress((void**)&U3h, g_U3h);
    cudaGetSymbolAddress((void**)&U3l, g_U3l);

    cudaFuncSetAttribute(wino_mma<true>,
        cudaFuncAttributeMaxDynamicSharedMemorySize, SMEM_BYTES);
    cudaFuncSetAttribute(wino_mma<false>,
        cudaFuncAttributeMaxDynamicSharedMemorySize, SMEM_BYTES);

    // weight transforms (tiny)
    wino_wtrans<<<(64 * 32 + 255) / 256, 256>>>(W2, U2h, U2l, 64, 64);
    wino_wtrans<<<(176 * 32 + 255) / 256, 256>>>(W3, U3h, U3l, 169, 176);

    // conv1: 1 -> 64, relu (direct)
    conv3x3_v3<1, 1, true><<<dim3(8, 8, BATCH * 4), dim3(16, 16)>>>(
        x, HW, HW, W1, b1, h1, HW, HW, 0, 64, 4);

    // conv2: 64 -> 64, relu (bf16-split mma winograd)
    wino_mma<true><<<dim3(16, 16, BATCH * 4), 256, SMEM_BYTES>>>(
        h1, U2h, U2l, b2, h2, HW, HW, 0, 64, 4, 64);

    // conv3: 64 -> 169 (pad 176, 11 groups), cropped interior (244x244, +6)
    wino_mma<false><<<dim3(16, 16, BATCH * 11), 256, SMEM_BYTES>>>(
        h2, U3h, U3l, b3, w, HO, HO, 6, 169, 11, 176);

    // final per-pixel 13x13 patch dot-product
    int n = BATCH * HO * HO;
    agg_kernel<<<(n + 255) / 256, 256>>>(x, y);
}

// round 11
// speedup vs baseline: 2.4030x; 1.4630x over previous
#include <cuda_runtime.h>
#include <cstdint>

#define BATCH 8
#define HW 256
#define KK 13
#define HO 244    // 256 - 13 + 1

// padded intermediate geometry: pixel (y,x) at [y+2][x+9], rows 268, stride 280
#define PH 268
#define PW 280
#define PSZ (PH * PW)       // 75040
#define HALO_PER_PLANE 9504 // 12*280 + 256*24

// ---- scratch (__device__ globals; no allocations allowed) ----
static __device__ float g_h1[(size_t)BATCH * 64 * PSZ];        // conv1 out (padded)
static __device__ float g_h2[(size_t)BATCH * 64 * PSZ];        // conv2 out (padded)
static __device__ float g_w [(size_t)BATCH * 169 * HO * HO];   // conv3 out
static __device__ float g_U2[(size_t)16 * 64 * 64];            // W2: [xi][cin][oc]
static __device__ float g_U3[(size_t)16 * 64 * 176];           // W3: [xi][cin][oc pad176]

__device__ __forceinline__ unsigned su(const void* p) {
    return (unsigned)__cvta_generic_to_shared(p);
}
__device__ __forceinline__ void cp4(unsigned dst, const void* src, int ok) {
    asm volatile("cp.async.ca.shared.global [%0], [%1], 4, %2;"
                 :: "r"(dst), "l"(src), "r"(ok ? 4 : 0));
}
__device__ __forceinline__ void cp16(unsigned dst, const void* src) {
    asm volatile("cp.async.cg.shared.global [%0], [%1], 16;"
                 :: "r"(dst), "l"(src));
}
#define CP_COMMIT() asm volatile("cp.async.commit_group;" ::: "memory")
#define CP_WAIT0()  asm volatile("cp.async.wait_group 0;"  ::: "memory")

// ---------------------------------------------------------------------------
// Zero the halo ring of both padded buffers (writers only touch the interior).
__global__ void zero_halo(float* a, float* b)
{
    long id = (long)blockIdx.x * 256 + threadIdx.x;
    const long half = (long)BATCH * 64 * HALO_PER_PLANE;
    if (id >= 2 * half) return;
    float* buf = (id < half) ? a : b;
    long r = id % half;
    int plane = (int)(r / HALO_PER_PLANE);
    int e = (int)(r % HALO_PER_PLANE);
    int row, col;
    if (e < 560)       { row = e / 280;            col = e % 280; }
    else if (e < 3360) { int f = e - 560; row = 258 + f / 280; col = f % 280; }
    else {
        int f = e - 3360;
        row = 2 + f / 24;
        int c24 = f % 24;
        col = (c24 < 9) ? c24 : 256 + c24;   // 9..23 -> 265..279
    }
    buf[(size_t)plane * PSZ + row * PW + col] = 0.f;
}

// ---------------------------------------------------------------------------
// Weight transform: U = G g G^T. Gmem layout U[xi][cin][ocPad] (oc contiguous,
// zero-padded to OCp so 16B staging needs no guards).
__global__ void wino_wtrans(const float* __restrict__ Wt, float* __restrict__ U,
                            int OC, int OCp)
{
    int id = blockIdx.x * 256 + threadIdx.x;
    if (id >= OCp * 64) return;
    int oc = id / 64, c = id % 64;
    float U16[16];
    if (oc < OC) {
        const float* g = Wt + ((size_t)oc * 64 + c) * 9;
        float u[4][3];
#pragma unroll
        for (int j = 0; j < 3; ++j) {
            float g0 = g[j], g1 = g[3 + j], g2 = g[6 + j];
            u[0][j] = g0;
            u[1][j] = 0.5f * (g0 + g1 + g2);
            u[2][j] = 0.5f * (g0 - g1 + g2);
            u[3][j] = g2;
        }
#pragma unroll
        for (int i = 0; i < 4; ++i) {
            float a = u[i][0], bb = u[i][1], cc = u[i][2];
            U16[i * 4 + 0] = a;
            U16[i * 4 + 1] = 0.5f * (a + bb + cc);
            U16[i * 4 + 2] = 0.5f * (a - bb + cc);
            U16[i * 4 + 3] = cc;
        }
    } else {
#pragma unroll
        for (int k = 0; k < 16; ++k) U16[k] = 0.f;
    }
#pragma unroll
    for (int xi = 0; xi < 16; ++xi)
        U[((size_t)xi * 64 + c) * OCp + oc] = U16[xi];
}

// ---------------------------------------------------------------------------
// Scalar Winograd F(2x2,3x3), padded input, all-cp16 staging, double-buffered.
// CTA: 16x16 outputs (64 tiles) x 16 oc. 8 chunks of 8 cin.
// smem floats: sIn 2x3456 (stride-24 rows) | sU 2x2560 (stride 20) |
//              sV 8704 (stride 68; sM aliases)
#define IN_OFF  0
#define U_OFF   6912
#define V_OFF   12032
#define SMEM_FLOATS 20736
#define SMEM_BYTES  (SMEM_FLOATS * 4)

template <bool RELU>
__global__ void __launch_bounds__(256, 2) wino_conv(
    const float* __restrict__ in,      // padded base for this problem
    const float* __restrict__ Ug, const float* __restrict__ bias,
    float* __restrict__ out, int outH, int outW,
    size_t outPlane, int outRowStr, int outYOff, int outXOff,
    int inOff, int OC, int ocGroups, int OCp)
{
    extern __shared__ float smf[];
    float* sInBuf[2] = { smf + IN_OFF, smf + IN_OFF + 3456 };
    float* sUBuf [2] = { smf + U_OFF,  smf + U_OFF + 2560 };
    float* sV = smf + V_OFF;   // (c*16 + xi)*68 + tile
    float* sM = smf + V_OFF;   // phase C alias: (oc*64 + tile)*17 + xi

    const int tid = threadIdx.x;
    const int xi  = tid & 15;
    const int ocg = (tid >> 4) & 1;
    const int tg  = tid >> 5;

    const int b  = blockIdx.z / ocGroups;
    const int og = blockIdx.z % ocGroups;
    const int ocBase = og * 16;
    const int x0 = blockIdx.x * 16, y0 = blockIdx.y * 16;

    const int delta   = (inOff + 8) & 3;            // even (0 or 2)
    const int colBase = x0 + ((inOff + 8) & ~3);
    const int rowBase = y0 + inOff + 1;
    const float* inB = in + (size_t)b * 64 * PSZ;

    // hoisted phase-A mapping (2 items per thread)
    int paSrc[2], paC16[2], paT[2];
#pragma unroll
    for (int q = 0; q < 2; ++q) {
        int p = tid + 256 * q;
        int c = p >> 6, t = p & 63;
        paSrc[q] = c * 432 + (t >> 3) * 48 + (t & 7) * 2 + delta;
        paC16[q] = c * 16;
        paT[q]   = t;
    }

    float acc[8][8];
#pragma unroll
    for (int j = 0; j < 8; ++j)
#pragma unroll
        for (int t = 0; t < 8; ++t) acc[j][t] = 0.f;

    // ---- async stage of one 8-cin chunk: all 16B, no guards ----
    auto stage = [&](int c0, float* sInD, float* sUD) {
        // input: 8 ch x 18 rows x 6 cp16 (24 floats/row) = 864 items
#pragma unroll
        for (int k = 0; k < 4; ++k) {
            int idx = tid + 256 * k;
            if (idx < 864) {
                int c  = idx / 108;
                int r  = idx - c * 108;
                int ry = r / 6, kk = r - ry * 6;
                cp16(su(sInD + c * 432 + ry * 24 + 4 * kk),
                     inB + ((size_t)(c0 + c) * PH + rowBase + ry) * PW
                         + colBase + 4 * kk);
            }
        }
        // U: 8 c x 16 xi x 4 quads = 512 items
#pragma unroll
        for (int k = 0; k < 2; ++k) {
            int idx = tid + 256 * k;
            int c  = idx >> 6;
            int r  = idx & 63;
            int x  = r >> 2, q = r & 3;
            cp16(su(sUD + (c * 16 + x) * 20 + 4 * q),
                 Ug + ((size_t)x * 64 + c0 + c) * OCp + ocBase + 4 * q);
        }
        CP_COMMIT();
    };

    stage(0, sInBuf[0], sUBuf[0]);

#pragma unroll 1
    for (int ci = 0; ci < 8; ++ci) {
        const int cur = ci & 1;
        float* sIn = sInBuf[cur];
        float* sU  = sUBuf[cur];

        CP_WAIT0();
        __syncthreads();
        if (ci < 7) stage((ci + 1) * 8, sInBuf[cur ^ 1], sUBuf[cur ^ 1]);

        // ---- phase A: V = B^T d B -> sV[c][xi][tile] ----
#pragma unroll
        for (int q = 0; q < 2; ++q) {
            const float2* base2 = (const float2*)(sIn + paSrc[q]);
            float d[4][4];
#pragma unroll
            for (int r = 0; r < 4; ++r) {
                float2 lo = base2[r * 12];
                float2 hi = base2[r * 12 + 1];
                d[r][0] = lo.x; d[r][1] = lo.y; d[r][2] = hi.x; d[r][3] = hi.y;
            }
            float z[4][4];
#pragma unroll
            for (int s = 0; s < 4; ++s) {
                z[0][s] = d[0][s] - d[2][s];
                z[1][s] = d[1][s] + d[2][s];
                z[2][s] = d[2][s] - d[1][s];
                z[3][s] = d[1][s] - d[3][s];
            }
#pragma unroll
            for (int i = 0; i < 4; ++i) {
                float* dst = sV + (paC16[q] + i * 4) * 68 + paT[q];
                dst[0]      = z[i][0] - z[i][2];
                dst[68]     = z[i][1] + z[i][2];
                dst[2 * 68] = z[i][2] - z[i][1];
                dst[3 * 68] = z[i][1] - z[i][3];
            }
        }
        __syncthreads();

        // ---- phase B: vectorized rank-1 updates per channel ----
#pragma unroll
        for (int c = 0; c < 8; ++c) {
            const float4 v0 = *(const float4*)&sV[(c * 16 + xi) * 68 + tg * 8];
            const float4 v1 = *(const float4*)&sV[(c * 16 + xi) * 68 + tg * 8 + 4];
            const float4 u0 = *(const float4*)&sU[(c * 16 + xi) * 20 + ocg * 8];
            const float4 u1 = *(const float4*)&sU[(c * 16 + xi) * 20 + ocg * 8 + 4];
            float vv[8] = { v0.x, v0.y, v0.z, v0.w, v1.x, v1.y, v1.z, v1.w };
            float uu[8] = { u0.x, u0.y, u0.z, u0.w, u1.x, u1.y, u1.z, u1.w };
#pragma unroll
            for (int j = 0; j < 8; ++j)
#pragma unroll
                for (int t = 0; t < 8; ++t)
                    acc[j][t] = fmaf(uu[j], vv[t], acc[j][t]);
        }
        __syncthreads();
    }

    // ---- phase C: Y = A^T M A, two oc halves via sM ----
#pragma unroll 1
    for (int h = 0; h < 2; ++h) {
        if (ocg == h) {
#pragma unroll
            for (int j = 0; j < 8; ++j)
#pragma unroll
                for (int t = 0; t < 8; ++t)
                    sM[(j * 64 + tg * 8 + t) * 17 + xi] = acc[j][t];
        }
        __syncthreads();
        for (int p = tid; p < 512; p += 256) {
            int oc = p >> 6, t = p & 63;
            int ocG = ocBase + h * 8 + oc;
            if (ocG < OC) {
                const float* src = sM + (oc * 64 + t) * 17;
                float m[4][4];
#pragma unroll
                for (int i = 0; i < 4; ++i)
#pragma unroll
                    for (int j = 0; j < 4; ++j) m[i][j] = src[i * 4 + j];
                float s0[4], s1[4];
#pragma unroll
                for (int j = 0; j < 4; ++j) {
                    s0[j] = m[0][j] + m[1][j] + m[2][j];
                    s1[j] = m[1][j] - m[2][j] - m[3][j];
                }
                float bv = bias[ocG];
                float y00 = s0[0] + s0[1] + s0[2] + bv;
                float y01 = s0[1] - s0[2] - s0[3] + bv;
                float y10 = s1[0] + s1[1] + s1[2] + bv;
                float y11 = s1[1] - s1[2] - s1[3] + bv;
                if (RELU) {
                    y00 = fmaxf(y00, 0.f); y01 = fmaxf(y01, 0.f);
                    y10 = fmaxf(y10, 0.f); y11 = fmaxf(y11, 0.f);
                }
                int oy = y0 + (t >> 3) * 2;
                int ox = x0 + (t & 7) * 2;
                float* o0 = out + (size_t)((size_t)b * OC + ocG) * outPlane
                          + (size_t)(oy + outYOff) * outRowStr + ox + outXOff;
                if (oy < outH) {
                    if (ox     < outW) o0[0] = y00;
                    if (ox + 1 < outW) o0[1] = y01;
                }
                if (oy + 1 < outH) {
                    if (ox     < outW) o0[outRowStr]     = y10;
                    if (ox + 1 < outW) o0[outRowStr + 1] = y11;
                }
            }
        }
        __syncthreads();
    }
}

// ---------------------------------------------------------------------------
// conv1 (1 -> 64): direct, register-tiled; writes the PADDED h1 buffer.
template <bool RELU>
__global__ void __launch_bounds__(256) conv1_direct(
    const float* __restrict__ in,
    const float* __restrict__ Wt, const float* __restrict__ bias,
    float* __restrict__ out)
{
    __shared__ float sIn[34][34];
    __shared__ float sW[16][9];

    const int tx = threadIdx.x, ty = threadIdx.y;
    const int tid = ty * 16 + tx;
    const int b  = blockIdx.z >> 2;
    const int og = blockIdx.z & 3;
    const int ocBase = og * 16;
    const int x0 = blockIdx.x * 32, y0 = blockIdx.y * 32;

    float acc[16][4];
#pragma unroll
    for (int o = 0; o < 16; ++o)
#pragma unroll
        for (int p = 0; p < 4; ++p) acc[o][p] = 0.f;

    const float* inB = in + (size_t)b * HW * HW;

    for (int idx = tid; idx < 34 * 34; idx += 256) {
        int ry = idx / 34, rx = idx % 34;
        int iy = y0 + ry - 1, ix = x0 + rx - 1;
        float v = 0.f;
        if (iy >= 0 && iy < HW && ix >= 0 && ix < HW)
            v = inB[(size_t)iy * HW + ix];
        sIn[ry][rx] = v;
    }
    for (int idx = tid; idx < 16 * 9; idx += 256)
        sW[idx / 9][idx % 9] = Wt[(size_t)(ocBase + idx / 9) * 9 + idx % 9];
    __syncthreads();

    float v[4][4];
#pragma unroll
    for (int u = 0; u < 4; ++u)
#pragma unroll
        for (int w = 0; w < 4; ++w)
            v[u][w] = sIn[2 * ty + u][2 * tx + w];
#pragma unroll
    for (int o = 0; o < 16; ++o) {
#pragma unroll
        for (int ky = 0; ky < 3; ++ky)
#pragma unroll
            for (int kx = 0; kx < 3; ++kx) {
                float wv = sW[o][ky * 3 + kx];
                acc[o][0] = fmaf(v[ky    ][kx    ], wv, acc[o][0]);
                acc[o][1] = fmaf(v[ky    ][kx + 1], wv, acc[o][1]);
                acc[o][2] = fmaf(v[ky + 1][kx    ], wv, acc[o][2]);
                acc[o][3] = fmaf(v[ky + 1][kx + 1], wv, acc[o][3]);
            }
    }

    const int ox = x0 + 2 * tx;
#pragma unroll
    for (int o = 0; o < 16; ++o) {
        int oc = ocBase + o;
        float bv = bias[oc];
        float* ob = out + (size_t)((size_t)b * 64 + oc) * PSZ;
#pragma unroll
        for (int py = 0; py < 2; ++py) {
            int oy = y0 + 2 * ty + py;
            float r0 = acc[o][2 * py] + bv;
            float r1 = acc[o][2 * py + 1] + bv;
            if (RELU) { r0 = fmaxf(r0, 0.f); r1 = fmaxf(r1, 0.f); }
            ob[(size_t)(oy + 2) * PW + ox + 9]     = r0;
            ob[(size_t)(oy + 2) * PW + ox + 1 + 9] = r1;
        }
    }
}

// y[b,i,j] = sum_{u,v} x[b, i+u, j+v] * w[b, u*13+v, i, j]
__global__ void __launch_bounds__(256) agg_kernel(
    const float* __restrict__ x, float* __restrict__ y)
{
    int id = blockIdx.x * 256 + threadIdx.x;
    if (id >= BATCH * HO * HO) return;
    int j = id % HO;
    int i = (id / HO) % HO;
    int b = id / (HO * HO);
    const float* xb = x + (size_t)b * HW * HW;
    const float* wb = g_w + (size_t)b * 169 * HO * HO + (size_t)i * HO + j;
    float acc = 0.f;
    for (int u = 0; u < KK; ++u) {
        const float* xr = xb + (size_t)(i + u) * HW + j;
#pragma unroll
        for (int v = 0; v < KK; ++v)
            acc = fmaf(xr[v], wb[(size_t)(u * KK + v) * HO * HO], acc);
    }
    y[id] = acc;
}

extern "C" void kernel_launch(void* const* d_in, const int* in_sizes, int n_in,
                              void* d_out, int out_size)
{
    const float* x  = (const float*)d_in[0];
    const float* W1 = (const float*)d_in[1];
    const float* b1 = (const float*)d_in[2];
    const float* W2 = (const float*)d_in[3];
    const float* b2 = (const float*)d_in[4];
    const float* W3 = (const float*)d_in[5];
    const float* b3 = (const float*)d_in[6];
    float* y = (float*)d_out;

    float *h1, *h2, *w, *U2, *U3;
    cudaGetSymbolAddress((void**)&h1, g_h1);
    cudaGetSymbolAddress((void**)&h2, g_h2);
    cudaGetSymbolAddress((void**)&w,  g_w);
    cudaGetSymbolAddress((void**)&U2, g_U2);
    cudaGetSymbolAddress((void**)&U3, g_U3);

    static int inited = 0;
    if (!inited) {
        cudaFuncSetAttribute(wino_conv<true>,
            cudaFuncAttributeMaxDynamicSharedMemorySize, SMEM_BYTES);
        cudaFuncSetAttribute(wino_conv<false>,
            cudaFuncAttributeMaxDynamicSharedMemorySize, SMEM_BYTES);
        inited = 1;
    }

    // halo zero + weight transforms (tiny)
    long nz = 2L * BATCH * 64 * HALO_PER_PLANE;
    zero_halo<<<(unsigned)((nz + 255) / 256), 256>>>(h1, h2);
    wino_wtrans<<<(64 * 64 + 255) / 256, 256>>>(W2, U2, 64, 64);
    wino_wtrans<<<(176 * 64 + 255) / 256, 256>>>(W3, U3, 169, 176);

    // conv1: 1 -> 64, relu (direct, writes padded h1)
    conv1_direct<true><<<dim3(8, 8, BATCH * 4), dim3(16, 16)>>>(x, W1, b1, h1);

    // conv2: 64 -> 64, relu (winograd, padded in/out)
    wino_conv<true><<<dim3(16, 16, BATCH * 4), 256, SMEM_BYTES>>>(
        h1, U2, b2, h2, HW, HW, (size_t)PSZ, PW, 2, 9, 0, 64, 4, 64);

    // conv3: 64 -> 169 (pad 176), cropped interior (244x244, +6), unpadded out
    wino_conv<false><<<dim3(16, 16, BATCH * 11), 256, SMEM_BYTES>>>(
        h2, U3, b3, w, HO, HO, (size_t)(HO * HO), HO, 0, 0, 6, 169, 11, 176);

    // final per-pixel 13x13 patch dot-product
    int n = BATCH * HO * HO;
    agg_kernel<<<(n + 255) / 256, 256>>>(x, y);
}